// round 4
// baseline (speedup 1.0000x reference)
#include <cuda_runtime.h>

// Problem constants
#define NB   4096      // utterance nodes
#define DIN  1856      // input feature dim
#define HH   128       // hidden dim
#define WB   191       // band half-width: tail < 15.2*exp(-19.1) ~ 7e-8, negligible vs 1e-3
#define BWID 383       // 2*WB+1
#define BSTR 384       // padded band row stride

// Persistent device scratch (allocation-free rule: __device__ globals)
__device__ float g_band[NB * BSTR];
__device__ float g_h [NB * HH];
__device__ float g_y [NB * HH];
__device__ float g_hn[NB * HH];
__device__ float g_z [NB * HH];
__device__ float g_acc[NB * HH];

// ---------------------------------------------------------------------------
// Kernel 1: build normalized band adjacency.
// One block per row i, 384 threads (thread t -> offset d = t - WB; t=383 pads 0).
// Row sum over the band only; omitted tail < 7e-8 absolute vs sum >= 1.
// ---------------------------------------------------------------------------
__global__ void __launch_bounds__(BSTR) build_band_kernel(
    const int* __restrict__ spk, const float* __restrict__ mmask)
{
    int i = blockIdx.x;
    int t = threadIdx.x;            // 0..383
    int d = t - WB;
    int j = i + d;

    float val = 0.0f;
    if (t < BWID && j >= 0 && j < NB) {
        if (d == 0) {
            val = 1.0f;
        } else {
            float temporal = expf(-0.1f * fabsf((float)d));
            if (spk[i] == spk[j]) {
                val = 0.8f * temporal;
            } else {
                float md = fabsf(mmask[i*3+0] - mmask[j*3+0])
                         + fabsf(mmask[i*3+1] - mmask[j*3+1])
                         + fabsf(mmask[i*3+2] - mmask[j*3+2]);
                float mod_sim = 1.0f - md * (1.0f/3.0f);
                val = 0.5f * temporal * mod_sim;
            }
        }
    }

    __shared__ float sd[BSTR];
    sd[t] = val;
    __syncthreads();
    for (int s = 256; s > 0; s >>= 1) {
        if (t < s && t + s < BSTR) sd[t] += sd[t + s];
        __syncthreads();
    }
    float inv = 1.0f / (sd[0] + 1e-8f);
    g_band[i * BSTR + t] = val * inv;
}

// ---------------------------------------------------------------------------
// Kernel 2: banded matvec  g_hn = band(adj) @ g_y     [NB,HH]
// Block: 16 output rows x all 128 cols, 128 threads.
//   thread col group: (tid&31)*4 .. +3 (float4),  row group: (tid>>5)*4 .. +3
// Window [r0-191, r0+15+191] streamed through smem in 7 chunks of 64 rows.
// Band slice [chunk_j x 16 rows] also staged in smem; inner loop is
// 2x LDS.128 (one broadcast) + 16 FFMA per j.
// ---------------------------------------------------------------------------
__global__ void __launch_bounds__(128) matvec_kernel()
{
    __shared__ __align__(16) float sm_h[64 * HH];   // 32 KB
    __shared__ __align__(16) float sm_b[64 * 16];   //  4 KB  layout [j][r]

    const int r0   = blockIdx.x * 16;
    const int tid  = threadIdx.x;
    const int col4 = (tid & 31) * 4;     // 4 cols
    const int trow = tid >> 5;           // rows trow*4 .. trow*4+3

    float acc[4][4];
#pragma unroll
    for (int a = 0; a < 4; a++)
#pragma unroll
        for (int b = 0; b < 4; b++) acc[a][b] = 0.0f;

    const int jstart = r0 - WB;

    for (int ch = 0; ch < 7; ch++) {
        const int j0 = jstart + ch * 64;

        // stage 64 rows of y (zero-padded OOB)
#pragma unroll
        for (int i = tid; i < 64 * 32; i += 128) {
            int row = i >> 5;
            int c4  = (i & 31) * 4;
            int gj  = j0 + row;
            float4 v = make_float4(0.f, 0.f, 0.f, 0.f);
            if (gj >= 0 && gj < NB)
                v = *(const float4*)&g_y[gj * HH + c4];
            *(float4*)&sm_h[row * HH + c4] = v;
        }
        // stage band slice: sm_b[j][r]
#pragma unroll
        for (int i = tid; i < 64 * 16; i += 128) {
            int jj = i >> 4;
            int r  = i & 15;
            int gj = j0 + jj;
            int gr = r0 + r;
            int dd = gj - gr + WB;
            float bv = 0.0f;
            if ((unsigned)dd < (unsigned)BWID && gj >= 0 && gj < NB)
                bv = g_band[gr * BSTR + dd];
            sm_b[jj * 16 + r] = bv;
        }
        __syncthreads();

#pragma unroll 4
        for (int j = 0; j < 64; j++) {
            float4 hv = *(float4*)&sm_h[j * HH + col4];
            float4 bv = *(float4*)&sm_b[j * 16 + trow * 4];   // warp-uniform broadcast
            acc[0][0] += bv.x * hv.x; acc[0][1] += bv.x * hv.y;
            acc[0][2] += bv.x * hv.z; acc[0][3] += bv.x * hv.w;
            acc[1][0] += bv.y * hv.x; acc[1][1] += bv.y * hv.y;
            acc[1][2] += bv.y * hv.z; acc[1][3] += bv.y * hv.w;
            acc[2][0] += bv.z * hv.x; acc[2][1] += bv.z * hv.y;
            acc[2][2] += bv.z * hv.z; acc[2][3] += bv.z * hv.w;
            acc[3][0] += bv.w * hv.x; acc[3][1] += bv.w * hv.y;
            acc[3][2] += bv.w * hv.z; acc[3][3] += bv.w * hv.w;
        }
        __syncthreads();
    }

#pragma unroll
    for (int rr = 0; rr < 4; rr++) {
        int r = r0 + trow * 4 + rr;
        float4 o = make_float4(acc[rr][0], acc[rr][1], acc[rr][2], acc[rr][3]);
        *(float4*)&g_hn[r * HH + col4] = o;
    }
}

// ---------------------------------------------------------------------------
// GEMM skeleton: C[4096,128] = A[4096,K] @ W[K,128] (+bias, +epilogue)
// Tile 32x64, BK=32, 128 threads, 4x4 microtile. grid(128, 2).
// As stored k-major with stride 40 floats (16B-aligned float4 frags).
// ---------------------------------------------------------------------------
#define ASTR 40

// --- projection: h0 = X @ Wp + bp ;  writes g_h and g_y ---
__global__ void __launch_bounds__(128) proj_kernel(
    const float* __restrict__ X, const float* __restrict__ Wp,
    const float* __restrict__ bp)
{
    __shared__ __align__(16) float As[32 * ASTR];
    __shared__ __align__(16) float Bs[32 * 64];
    const int m0 = blockIdx.x * 32;
    const int n0 = blockIdx.y * 64;
    const int tid  = threadIdx.x;
    const int trow = tid >> 4;         // 0..7
    const int tcol = tid & 15;         // 0..15
    const int am = tid >> 3;           // 0..15 (+16)
    const int ak = (tid & 7) * 4;
    const int bk = tid >> 4;           // 0..7 (+8,+16,+24)
    const int bn = (tid & 15) * 4;

    float acc[4][4];
#pragma unroll
    for (int a = 0; a < 4; a++)
#pragma unroll
        for (int b = 0; b < 4; b++) acc[a][b] = 0.0f;

    for (int k0 = 0; k0 < DIN; k0 += 32) {
#pragma unroll
        for (int mm2 = 0; mm2 < 2; mm2++) {
            int m = am + mm2 * 16;
            float4 v = *(const float4*)&X[(m0 + m) * DIN + k0 + ak];
            As[(ak+0)*ASTR + m] = v.x; As[(ak+1)*ASTR + m] = v.y;
            As[(ak+2)*ASTR + m] = v.z; As[(ak+3)*ASTR + m] = v.w;
        }
#pragma unroll
        for (int kk2 = 0; kk2 < 4; kk2++) {
            int k = bk + kk2 * 8;
            *(float4*)&Bs[k * 64 + bn] = *(const float4*)&Wp[(k0 + k) * HH + n0 + bn];
        }
        __syncthreads();
#pragma unroll
        for (int k = 0; k < 32; k++) {
            float4 a = *(float4*)&As[k * ASTR + trow * 4];
            float4 b = *(float4*)&Bs[k * 64 + tcol * 4];
            acc[0][0]+=a.x*b.x; acc[0][1]+=a.x*b.y; acc[0][2]+=a.x*b.z; acc[0][3]+=a.x*b.w;
            acc[1][0]+=a.y*b.x; acc[1][1]+=a.y*b.y; acc[1][2]+=a.y*b.z; acc[1][3]+=a.y*b.w;
            acc[2][0]+=a.z*b.x; acc[2][1]+=a.z*b.y; acc[2][2]+=a.z*b.z; acc[2][3]+=a.z*b.w;
            acc[3][0]+=a.w*b.x; acc[3][1]+=a.w*b.y; acc[3][2]+=a.w*b.z; acc[3][3]+=a.w*b.w;
        }
        __syncthreads();
    }
    float4 bb = *(const float4*)&bp[n0 + tcol * 4];
#pragma unroll
    for (int i = 0; i < 4; i++) {
        int m = m0 + trow * 4 + i;
        float4 o = make_float4(acc[i][0]+bb.x, acc[i][1]+bb.y, acc[i][2]+bb.z, acc[i][3]+bb.w);
        *(float4*)&g_h[m * HH + n0 + tcol * 4] = o;
        *(float4*)&g_y[m * HH + n0 + tcol * 4] = o;
    }
}

// --- mlp1: z = tanh([y | hn] @ W1 + b1) ---
__global__ void __launch_bounds__(128) mlp1_kernel(
    const float* __restrict__ W1, const float* __restrict__ b1)
{
    __shared__ __align__(16) float As[32 * ASTR];
    __shared__ __align__(16) float Bs[32 * 64];
    const int m0 = blockIdx.x * 32;
    const int n0 = blockIdx.y * 64;
    const int tid  = threadIdx.x;
    const int trow = tid >> 4;
    const int tcol = tid & 15;
    const int am = tid >> 3;
    const int ak = (tid & 7) * 4;
    const int bk = tid >> 4;
    const int bn = (tid & 15) * 4;

    float acc[4][4];
#pragma unroll
    for (int a = 0; a < 4; a++)
#pragma unroll
        for (int b = 0; b < 4; b++) acc[a][b] = 0.0f;

    for (int k0 = 0; k0 < 2 * HH; k0 += 32) {
        const float* src = (k0 < HH) ? g_y : g_hn;
        int c0 = k0 & (HH - 1);
#pragma unroll
        for (int mm2 = 0; mm2 < 2; mm2++) {
            int m = am + mm2 * 16;
            float4 v = *(const float4*)&src[(m0 + m) * HH + c0 + ak];
            As[(ak+0)*ASTR + m] = v.x; As[(ak+1)*ASTR + m] = v.y;
            As[(ak+2)*ASTR + m] = v.z; As[(ak+3)*ASTR + m] = v.w;
        }
#pragma unroll
        for (int kk2 = 0; kk2 < 4; kk2++) {
            int k = bk + kk2 * 8;
            *(float4*)&Bs[k * 64 + bn] = *(const float4*)&W1[(k0 + k) * HH + n0 + bn];
        }
        __syncthreads();
#pragma unroll
        for (int k = 0; k < 32; k++) {
            float4 a = *(float4*)&As[k * ASTR + trow * 4];
            float4 b = *(float4*)&Bs[k * 64 + tcol * 4];
            acc[0][0]+=a.x*b.x; acc[0][1]+=a.x*b.y; acc[0][2]+=a.x*b.z; acc[0][3]+=a.x*b.w;
            acc[1][0]+=a.y*b.x; acc[1][1]+=a.y*b.y; acc[1][2]+=a.y*b.z; acc[1][3]+=a.y*b.w;
            acc[2][0]+=a.z*b.x; acc[2][1]+=a.z*b.y; acc[2][2]+=a.z*b.z; acc[2][3]+=a.z*b.w;
            acc[3][0]+=a.w*b.x; acc[3][1]+=a.w*b.y; acc[3][2]+=a.w*b.z; acc[3][3]+=a.w*b.w;
        }
        __syncthreads();
    }
    float4 bb = *(const float4*)&b1[n0 + tcol * 4];
#pragma unroll
    for (int i = 0; i < 4; i++) {
        int m = m0 + trow * 4 + i;
        float4 o = make_float4(tanhf(acc[i][0]+bb.x), tanhf(acc[i][1]+bb.y),
                               tanhf(acc[i][2]+bb.z), tanhf(acc[i][3]+bb.w));
        *(float4*)&g_z[m * HH + n0 + tcol * 4] = o;
    }
}

// --- mlp2: k = z @ W2 + b2, fused RK4-stage epilogue ---
// stage s: acc_{new} = (init ? h : acc) + w*k ;  y = h + c*k  (stages 0-2)
//          stage 3:  h = y = acc_{new}; optionally write d_out.
__global__ void __launch_bounds__(128) mlp2_kernel(
    const float* __restrict__ W2, const float* __restrict__ b2,
    float wacc, float cy, int initAcc, int writeH, float* __restrict__ outp)
{
    __shared__ __align__(16) float As[32 * ASTR];
    __shared__ __align__(16) float Bs[32 * 64];
    const int m0 = blockIdx.x * 32;
    const int n0 = blockIdx.y * 64;
    const int tid  = threadIdx.x;
    const int trow = tid >> 4;
    const int tcol = tid & 15;
    const int am = tid >> 3;
    const int ak = (tid & 7) * 4;
    const int bk = tid >> 4;
    const int bn = (tid & 15) * 4;

    float acc[4][4];
#pragma unroll
    for (int a = 0; a < 4; a++)
#pragma unroll
        for (int b = 0; b < 4; b++) acc[a][b] = 0.0f;

    for (int k0 = 0; k0 < HH; k0 += 32) {
#pragma unroll
        for (int mm2 = 0; mm2 < 2; mm2++) {
            int m = am + mm2 * 16;
            float4 v = *(const float4*)&g_z[(m0 + m) * HH + k0 + ak];
            As[(ak+0)*ASTR + m] = v.x; As[(ak+1)*ASTR + m] = v.y;
            As[(ak+2)*ASTR + m] = v.z; As[(ak+3)*ASTR + m] = v.w;
        }
#pragma unroll
        for (int kk2 = 0; kk2 < 4; kk2++) {
            int k = bk + kk2 * 8;
            *(float4*)&Bs[k * 64 + bn] = *(const float4*)&W2[(k0 + k) * HH + n0 + bn];
        }
        __syncthreads();
#pragma unroll
        for (int k = 0; k < 32; k++) {
            float4 a = *(float4*)&As[k * ASTR + trow * 4];
            float4 b = *(float4*)&Bs[k * 64 + tcol * 4];
            acc[0][0]+=a.x*b.x; acc[0][1]+=a.x*b.y; acc[0][2]+=a.x*b.z; acc[0][3]+=a.x*b.w;
            acc[1][0]+=a.y*b.x; acc[1][1]+=a.y*b.y; acc[1][2]+=a.y*b.z; acc[1][3]+=a.y*b.w;
            acc[2][0]+=a.z*b.x; acc[2][1]+=a.z*b.y; acc[2][2]+=a.z*b.z; acc[2][3]+=a.z*b.w;
            acc[3][0]+=a.w*b.x; acc[3][1]+=a.w*b.y; acc[3][2]+=a.w*b.z; acc[3][3]+=a.w*b.w;
        }
        __syncthreads();
    }
    float4 bb = *(const float4*)&b2[n0 + tcol * 4];
#pragma unroll
    for (int i = 0; i < 4; i++) {
        int m = m0 + trow * 4 + i;
        int idx = m * HH + n0 + tcol * 4;
        float4 kv = make_float4(acc[i][0]+bb.x, acc[i][1]+bb.y, acc[i][2]+bb.z, acc[i][3]+bb.w);
        float4 h4 = *(const float4*)&g_h[idx];
        float4 base = initAcc ? h4 : *(const float4*)&g_acc[idx];
        float4 an = make_float4(base.x + wacc*kv.x, base.y + wacc*kv.y,
                                base.z + wacc*kv.z, base.w + wacc*kv.w);
        *(float4*)&g_acc[idx] = an;
        if (writeH) {
            *(float4*)&g_h[idx] = an;
            *(float4*)&g_y[idx] = an;
            if (outp) *(float4*)&outp[idx] = an;
        } else {
            float4 yn = make_float4(h4.x + cy*kv.x, h4.y + cy*kv.y,
                                    h4.z + cy*kv.z, h4.w + cy*kv.w);
            *(float4*)&g_y[idx] = yn;
        }
    }
}

// ---------------------------------------------------------------------------
extern "C" void kernel_launch(void* const* d_in, const int* in_sizes, int n_in,
                              void* d_out, int out_size)
{
    (void)in_sizes; (void)n_in; (void)out_size;
    const float* features = (const float*)d_in[0];
    const int*   spk      = (const int*)  d_in[1];
    const float* mmask    = (const float*)d_in[2];
    const float* Wp       = (const float*)d_in[3];
    const float* bp       = (const float*)d_in[4];
    const float* W1       = (const float*)d_in[5];
    const float* b1       = (const float*)d_in[6];
    const float* W2       = (const float*)d_in[7];
    const float* b2       = (const float*)d_in[8];
    float* out = (float*)d_out;

    build_band_kernel<<<NB, BSTR>>>(spk, mmask);

    dim3 ggrid(NB / 32, HH / 64);
    proj_kernel<<<ggrid, 128>>>(features, Wp, bp);

    const float dt = 1.0f / 4.0f;
    for (int step = 0; step < 4; step++) {
        for (int s = 0; s < 4; s++) {
            matvec_kernel<<<NB / 16, 128>>>();
            mlp1_kernel<<<ggrid, 128>>>(W1, b1);
            float w  = (s == 0 || s == 3) ? dt / 6.0f : dt / 3.0f;
            float c  = (s == 2) ? dt : 0.5f * dt;
            int init = (s == 0);
            int wh   = (s == 3);
            float* op = (step == 3 && s == 3) ? out : nullptr;
            mlp2_kernel<<<ggrid, 128>>>(W2, b2, w, c, init, wh, op);
        }
    }
}

// round 5
// speedup vs baseline: 1.3133x; 1.3133x over previous
#include <cuda_runtime.h>

// Problem constants
#define NB   4096
#define DIN  1856
#define HH   128
#define WB   191       // band half-width: tail < 7e-8 absolute, negligible vs 1e-3
#define BWID 383
#define BSTR 384
#define GRID 128       // persistent blocks (<=148 SMs -> all co-resident, wave 1)
#define RPB  32        // rows per block

// Persistent device scratch (allocation-free rule: __device__ globals)
__device__ float g_band[NB * BSTR];
__device__ float g_h[NB * HH];
__device__ float g_ybuf[2][NB * HH];     // ping-pong y buffers
__device__ int g_bar_count = 0;
__device__ unsigned g_bar_gen = 0;

// ---------------------------------------------------------------------------
// Grid-wide barrier (all GRID blocks resident by construction).
// ---------------------------------------------------------------------------
__device__ __forceinline__ void grid_sync_dev()
{
    __syncthreads();
    if (threadIdx.x == 0) {
        __threadfence();
        unsigned gen = *((volatile unsigned*)&g_bar_gen);
        if (atomicAdd(&g_bar_count, 1) == (int)gridDim.x - 1) {
            g_bar_count = 0;
            __threadfence();
            *((volatile unsigned*)&g_bar_gen) = gen + 1;
        } else {
            while (*((volatile unsigned*)&g_bar_gen) == gen) { }
        }
        __threadfence();
    }
    __syncthreads();
}

// ---------------------------------------------------------------------------
// Kernel 1: build normalized band adjacency. One block per row.
// ---------------------------------------------------------------------------
__global__ void __launch_bounds__(BSTR) build_band_kernel(
    const int* __restrict__ spk, const float* __restrict__ mmask)
{
    int i = blockIdx.x;
    int t = threadIdx.x;            // 0..383
    int d = t - WB;
    int j = i + d;

    float val = 0.0f;
    if (t < BWID && j >= 0 && j < NB) {
        if (d == 0) {
            val = 1.0f;
        } else {
            float temporal = expf(-0.1f * fabsf((float)d));
            if (spk[i] == spk[j]) {
                val = 0.8f * temporal;
            } else {
                float md = fabsf(mmask[i*3+0] - mmask[j*3+0])
                         + fabsf(mmask[i*3+1] - mmask[j*3+1])
                         + fabsf(mmask[i*3+2] - mmask[j*3+2]);
                float mod_sim = 1.0f - md * (1.0f/3.0f);
                val = 0.5f * temporal * mod_sim;
            }
        }
    }

    __shared__ float sd[BSTR];
    sd[t] = val;
    __syncthreads();
    for (int s = 256; s > 0; s >>= 1) {
        if (t < s && t + s < BSTR) sd[t] += sd[t + s];
        __syncthreads();
    }
    float inv = 1.0f / (sd[0] + 1e-8f);
    g_band[i * BSTR + t] = val * inv;
}

// ---------------------------------------------------------------------------
// Kernel 2: projection h0 = X @ Wp + bp.  Tile 32x128, 256 threads, grid 128.
// A^T staged in smem with pad-33 stride; inner loop 4 broadcast LDS + LDS.128
// + 16 FFMA.
// ---------------------------------------------------------------------------
__global__ void __launch_bounds__(256) proj_kernel(
    const float* __restrict__ X, const float* __restrict__ Wp,
    const float* __restrict__ bp)
{
    __shared__ __align__(16) float As[32 * 33];
    __shared__ __align__(16) float Bs[32 * 128];
    const int m0  = blockIdx.x * RPB;
    const int tid = threadIdx.x;
    const int rg  = tid >> 5;       // 0..7  -> rows 4rg..4rg+3
    const int cg  = tid & 31;       // 0..31 -> cols 4cg..4cg+3
    const int lr  = tid >> 3;       // 0..31 (A stage row)
    const int lk4 = (tid & 7) * 4;  // A stage k

    float acc[4][4];
#pragma unroll
    for (int a = 0; a < 4; a++)
#pragma unroll
        for (int b = 0; b < 4; b++) acc[a][b] = 0.0f;

    for (int k0 = 0; k0 < DIN; k0 += 32) {
        float4 v = *(const float4*)&X[(m0 + lr) * DIN + k0 + lk4];
        As[(lk4+0)*33 + lr] = v.x; As[(lk4+1)*33 + lr] = v.y;
        As[(lk4+2)*33 + lr] = v.z; As[(lk4+3)*33 + lr] = v.w;
#pragma unroll
        for (int i = tid; i < 1024; i += 256) {
            int k = i >> 5, c4 = (i & 31) * 4;
            *(float4*)&Bs[k*128 + c4] = *(const float4*)&Wp[(k0 + k) * HH + c4];
        }
        __syncthreads();
#pragma unroll 8
        for (int k = 0; k < 32; k++) {
            float a0 = As[k*33 + 4*rg + 0], a1 = As[k*33 + 4*rg + 1];
            float a2 = As[k*33 + 4*rg + 2], a3 = As[k*33 + 4*rg + 3];
            float4 b = *(float4*)&Bs[k*128 + 4*cg];
            acc[0][0]+=a0*b.x; acc[0][1]+=a0*b.y; acc[0][2]+=a0*b.z; acc[0][3]+=a0*b.w;
            acc[1][0]+=a1*b.x; acc[1][1]+=a1*b.y; acc[1][2]+=a1*b.z; acc[1][3]+=a1*b.w;
            acc[2][0]+=a2*b.x; acc[2][1]+=a2*b.y; acc[2][2]+=a2*b.z; acc[2][3]+=a2*b.w;
            acc[3][0]+=a3*b.x; acc[3][1]+=a3*b.y; acc[3][2]+=a3*b.z; acc[3][3]+=a3*b.w;
        }
        __syncthreads();
    }
    float4 bb = *(const float4*)&bp[4*cg];
#pragma unroll
    for (int i = 0; i < 4; i++) {
        int m = m0 + 4*rg + i;
        float4 o = make_float4(acc[i][0]+bb.x, acc[i][1]+bb.y,
                               acc[i][2]+bb.z, acc[i][3]+bb.w);
        *(float4*)&g_h[m * HH + 4*cg]       = o;
        *(float4*)&g_ybuf[0][m * HH + 4*cg] = o;
    }
}

// ---------------------------------------------------------------------------
// Kernel 3: persistent ODE kernel. All 16 RK4 stages in one launch.
// Per stage: band matvec -> mlp1(tanh) -> mlp2 -> RK4 epilogue -> grid sync.
// h and RK4 accumulator live in registers; hn/z/[y|hn]^T in smem.
// ---------------------------------------------------------------------------
#define SMEM_FLOATS (256*33 + 64*128 + 64*33 + 32*128)   // 22848 floats
#define SMEM_BYTES  (SMEM_FLOATS * 4)                    // 91392 B

__global__ void __launch_bounds__(256, 1) ode_kernel(
    const float* __restrict__ W1, const float* __restrict__ b1,
    const float* __restrict__ W2, const float* __restrict__ b2,
    float* __restrict__ outp)
{
    extern __shared__ float smem[];
    float* sAt = smem;              // [256][33]  A^T for MLPs (y^T | hn^T, then z^T)
    float* sY  = sAt + 256*33;      // [64][128]  y window chunk
    float* sB  = sY  + 64*128;      // [64][33]   band slice [j][r], padded
    float* sW  = sB  + 64*33;       // [32][128]  weight tile

    const int tid = threadIdx.x;
    const int rg  = tid >> 5;       // rows 4rg..4rg+3
    const int cg  = tid & 31;       // cols 4cg..4cg+3
    const int r0  = blockIdx.x * RPB;

    // persistent register state
    float hreg[4][4], rk[4][4];
#pragma unroll
    for (int i = 0; i < 4; i++) {
        float4 v = *(const float4*)&g_h[(r0 + 4*rg + i) * HH + 4*cg];
        hreg[i][0]=v.x; hreg[i][1]=v.y; hreg[i][2]=v.z; hreg[i][3]=v.w;
    }
    float4 b1v = *(const float4*)&b1[4*cg];
    float4 b2v = *(const float4*)&b2[4*cg];
    const float dt = 0.25f;

#pragma unroll 1
    for (int st = 0; st < 16; st++) {
        const int s = st & 3;
        const float* __restrict__ yin  = g_ybuf[st & 1];
        float* __restrict__       yout = g_ybuf[(st + 1) & 1];

        // ---- banded matvec: acc = band @ yin for rows r0..r0+31 ----
        float acc[4][4];
#pragma unroll
        for (int a = 0; a < 4; a++)
#pragma unroll
            for (int b = 0; b < 4; b++) acc[a][b] = 0.0f;

        for (int ch = 0; ch < 7; ch++) {
            const int j0 = r0 - WB + ch * 64;
#pragma unroll
            for (int i = tid; i < 2048; i += 256) {     // y chunk: 64 rows x 32 float4
                int row = i >> 5, c4 = (i & 31) * 4;
                int gj = j0 + row;
                float4 v = make_float4(0.f, 0.f, 0.f, 0.f);
                if (gj >= 0 && gj < NB)
                    v = *(const float4*)&yin[gj * HH + c4];
                *(float4*)&sY[row * 128 + c4] = v;
            }
#pragma unroll
            for (int i = tid; i < 2048; i += 256) {     // band slice: coalesced per row
                int r = i >> 6, jj = i & 63;
                int gr = r0 + r;
                int gj = j0 + jj;
                int dd = gj - gr + WB;
                float bv = 0.0f;
                if ((unsigned)dd < (unsigned)BWID && gj >= 0 && gj < NB)
                    bv = g_band[gr * BSTR + dd];
                sB[jj * 33 + r] = bv;
            }
            __syncthreads();
#pragma unroll 4
            for (int j = 0; j < 64; j++) {
                float4 hv = *(float4*)&sY[j * 128 + 4*cg];
                float bv0 = sB[j*33 + 4*rg + 0], bv1 = sB[j*33 + 4*rg + 1];
                float bv2 = sB[j*33 + 4*rg + 2], bv3 = sB[j*33 + 4*rg + 3];
                acc[0][0]+=bv0*hv.x; acc[0][1]+=bv0*hv.y; acc[0][2]+=bv0*hv.z; acc[0][3]+=bv0*hv.w;
                acc[1][0]+=bv1*hv.x; acc[1][1]+=bv1*hv.y; acc[1][2]+=bv1*hv.z; acc[1][3]+=bv1*hv.w;
                acc[2][0]+=bv2*hv.x; acc[2][1]+=bv2*hv.y; acc[2][2]+=bv2*hv.z; acc[2][3]+=bv2*hv.w;
                acc[3][0]+=bv3*hv.x; acc[3][1]+=bv3*hv.y; acc[3][2]+=bv3*hv.z; acc[3][3]+=bv3*hv.w;
            }
            __syncthreads();
        }

        // stage y_own^T (conflict-free: addr%32 == c%32) and hn^T into sAt
#pragma unroll
        for (int i = tid; i < 4096; i += 256) {
            int r = i >> 7, c = i & 127;
            sAt[c * 33 + r] = yin[(r0 + r) * HH + c];
        }
#pragma unroll
        for (int i = 0; i < 4; i++)
#pragma unroll
            for (int j = 0; j < 4; j++)
                sAt[(128 + 4*cg + j) * 33 + 4*rg + i] = acc[i][j];
        __syncthreads();

        // ---- mlp1: z = tanh([y|hn] @ W1 + b1) ----
#pragma unroll
        for (int a = 0; a < 4; a++)
#pragma unroll
            for (int b = 0; b < 4; b++) acc[a][b] = 0.0f;
        for (int kc = 0; kc < 8; kc++) {
#pragma unroll
            for (int i = tid; i < 1024; i += 256) {
                int k = i >> 5, c4 = (i & 31) * 4;
                *(float4*)&sW[k*128 + c4] = *(const float4*)&W1[(kc*32 + k) * HH + c4];
            }
            __syncthreads();
#pragma unroll 8
            for (int k = 0; k < 32; k++) {
                int kk = kc * 32 + k;
                float a0 = sAt[kk*33 + 4*rg + 0], a1 = sAt[kk*33 + 4*rg + 1];
                float a2 = sAt[kk*33 + 4*rg + 2], a3 = sAt[kk*33 + 4*rg + 3];
                float4 b = *(float4*)&sW[k*128 + 4*cg];
                acc[0][0]+=a0*b.x; acc[0][1]+=a0*b.y; acc[0][2]+=a0*b.z; acc[0][3]+=a0*b.w;
                acc[1][0]+=a1*b.x; acc[1][1]+=a1*b.y; acc[1][2]+=a1*b.z; acc[1][3]+=a1*b.w;
                acc[2][0]+=a2*b.x; acc[2][1]+=a2*b.y; acc[2][2]+=a2*b.z; acc[2][3]+=a2*b.w;
                acc[3][0]+=a3*b.x; acc[3][1]+=a3*b.y; acc[3][2]+=a3*b.z; acc[3][3]+=a3*b.w;
            }
            __syncthreads();
        }
        // z = tanh(acc + b1); write z^T into sAt rows 0..127
        {
            float bb[4] = {b1v.x, b1v.y, b1v.z, b1v.w};
#pragma unroll
            for (int i = 0; i < 4; i++)
#pragma unroll
                for (int j = 0; j < 4; j++)
                    sAt[(4*cg + j) * 33 + 4*rg + i] = tanhf(acc[i][j] + bb[j]);
        }
        __syncthreads();

        // ---- mlp2: k = z @ W2 + b2 ----
#pragma unroll
        for (int a = 0; a < 4; a++)
#pragma unroll
            for (int b = 0; b < 4; b++) acc[a][b] = 0.0f;
        for (int kc = 0; kc < 4; kc++) {
#pragma unroll
            for (int i = tid; i < 1024; i += 256) {
                int k = i >> 5, c4 = (i & 31) * 4;
                *(float4*)&sW[k*128 + c4] = *(const float4*)&W2[(kc*32 + k) * HH + c4];
            }
            __syncthreads();
#pragma unroll 8
            for (int k = 0; k < 32; k++) {
                int kk = kc * 32 + k;
                float a0 = sAt[kk*33 + 4*rg + 0], a1 = sAt[kk*33 + 4*rg + 1];
                float a2 = sAt[kk*33 + 4*rg + 2], a3 = sAt[kk*33 + 4*rg + 3];
                float4 b = *(float4*)&sW[k*128 + 4*cg];
                acc[0][0]+=a0*b.x; acc[0][1]+=a0*b.y; acc[0][2]+=a0*b.z; acc[0][3]+=a0*b.w;
                acc[1][0]+=a1*b.x; acc[1][1]+=a1*b.y; acc[1][2]+=a1*b.z; acc[1][3]+=a1*b.w;
                acc[2][0]+=a2*b.x; acc[2][1]+=a2*b.y; acc[2][2]+=a2*b.z; acc[2][3]+=a2*b.w;
                acc[3][0]+=a3*b.x; acc[3][1]+=a3*b.y; acc[3][2]+=a3*b.z; acc[3][3]+=a3*b.w;
            }
            __syncthreads();
        }

        // ---- RK4 epilogue (registers) ----
        {
            const float wq = (s == 0 || s == 3) ? dt * (1.0f/6.0f) : dt * (1.0f/3.0f);
            const float cq = (s == 2) ? dt : 0.5f * dt;
            float bb[4] = {b2v.x, b2v.y, b2v.z, b2v.w};
#pragma unroll
            for (int i = 0; i < 4; i++) {
                float yn[4];
#pragma unroll
                for (int j = 0; j < 4; j++) {
                    float kv = acc[i][j] + bb[j];
                    if (s == 0) rk[i][j] = hreg[i][j] + wq * kv;
                    else        rk[i][j] += wq * kv;
                    if (s == 3) { hreg[i][j] = rk[i][j]; yn[j] = rk[i][j]; }
                    else        yn[j] = hreg[i][j] + cq * kv;
                }
                int idx = (r0 + 4*rg + i) * HH + 4*cg;
                float4 o = make_float4(yn[0], yn[1], yn[2], yn[3]);
                *(float4*)&yout[idx] = o;
                if (st == 15) *(float4*)&outp[idx] = o;
            }
        }

        grid_sync_dev();
    }
}

// ---------------------------------------------------------------------------
extern "C" void kernel_launch(void* const* d_in, const int* in_sizes, int n_in,
                              void* d_out, int out_size)
{
    (void)in_sizes; (void)n_in; (void)out_size;
    const float* features = (const float*)d_in[0];
    const int*   spk      = (const int*)  d_in[1];
    const float* mmask    = (const float*)d_in[2];
    const float* Wp       = (const float*)d_in[3];
    const float* bp       = (const float*)d_in[4];
    const float* W1       = (const float*)d_in[5];
    const float* b1       = (const float*)d_in[6];
    const float* W2       = (const float*)d_in[7];
    const float* b2       = (const float*)d_in[8];
    float* out = (float*)d_out;

    static int attr_done = 0;
    if (!attr_done) {
        cudaFuncSetAttribute(ode_kernel,
                             cudaFuncAttributeMaxDynamicSharedMemorySize,
                             SMEM_BYTES);
        attr_done = 1;
    }

    build_band_kernel<<<NB, BSTR>>>(spk, mmask);
    proj_kernel<<<GRID, 256>>>(features, Wp, bp);
    ode_kernel<<<GRID, 256, SMEM_BYTES>>>(W1, b1, W2, b2, out);
}

// round 6
// speedup vs baseline: 1.4596x; 1.1115x over previous
#include <cuda_runtime.h>

// Problem constants
#define NB   4096
#define DIN  1856
#define HH   128
#define WB   191       // band half-width: tail < 7e-8 absolute, negligible vs 1e-3
#define BWID 383
#define BSTR 384
#define GRID 128       // persistent blocks, all co-resident
#define RPB  32        // rows per block
#define CH   48        // matvec chunk rows
#define NCH  9         // ceil((383+31)/48)
#define SA   36        // transposed-activation stride (mult of 4 -> 16B aligned rows)

typedef unsigned long long ull;

// Persistent device scratch
__device__ float g_band[NB * BSTR];
__device__ float g_h[NB * HH];
__device__ float g_ybuf[2][NB * HH];
__device__ int g_bar_count = 0;
__device__ unsigned g_bar_gen = 0;

// ---------------------------------------------------------------------------
// f32x2 packed-math helpers
// ---------------------------------------------------------------------------
__device__ __forceinline__ ull dup2(float x) {
    ull r; asm("mov.b64 %0, {%1, %1};" : "=l"(r) : "f"(x)); return r;
}
__device__ __forceinline__ void ffma2(ull& d, ull a, ull b) {
    asm("fma.rn.f32x2 %0, %1, %2, %0;" : "+l"(d) : "l"(a), "l"(b));
}
__device__ __forceinline__ float2 unpk(ull v) {
    float2 f; asm("mov.b64 {%0, %1}, %2;" : "=f"(f.x), "=f"(f.y) : "l"(v));
    return f;
}

// 8 rows x 2 cols microtile step: rows paired in f32x2 (free via LDS.128),
// 2-col operand duplicated via mov.b64 {x,x}.
__device__ __forceinline__ void step8(ull acc[4][2],
                                      const float* __restrict__ aBase,
                                      const float* __restrict__ bBase)
{
    ulonglong2 a1 = *(const ulonglong2*)(aBase);       // rows (0,1),(2,3)
    ulonglong2 a2 = *(const ulonglong2*)(aBase + 4);   // rows (4,5),(6,7)
    float2 wv = *(const float2*)(bBase);
    ull w0 = dup2(wv.x), w1 = dup2(wv.y);
    ffma2(acc[0][0], a1.x, w0); ffma2(acc[0][1], a1.x, w1);
    ffma2(acc[1][0], a1.y, w0); ffma2(acc[1][1], a1.y, w1);
    ffma2(acc[2][0], a2.x, w0); ffma2(acc[2][1], a2.x, w1);
    ffma2(acc[3][0], a2.y, w0); ffma2(acc[3][1], a2.y, w1);
}

// ---------------------------------------------------------------------------
// Grid-wide barrier (all GRID blocks resident by construction).
// ---------------------------------------------------------------------------
__device__ __forceinline__ void grid_sync_dev()
{
    __syncthreads();
    if (threadIdx.x == 0) {
        __threadfence();
        unsigned gen = *((volatile unsigned*)&g_bar_gen);
        if (atomicAdd(&g_bar_count, 1) == (int)gridDim.x - 1) {
            g_bar_count = 0;
            __threadfence();
            *((volatile unsigned*)&g_bar_gen) = gen + 1;
        } else {
            while (*((volatile unsigned*)&g_bar_gen) == gen) { }
        }
        __threadfence();
    }
    __syncthreads();
}

// ---------------------------------------------------------------------------
// Kernel 1: build normalized band adjacency. One block per row.
// ---------------------------------------------------------------------------
__global__ void __launch_bounds__(BSTR) build_band_kernel(
    const int* __restrict__ spk, const float* __restrict__ mmask)
{
    int i = blockIdx.x;
    int t = threadIdx.x;
    int d = t - WB;
    int j = i + d;

    float val = 0.0f;
    if (t < BWID && j >= 0 && j < NB) {
        if (d == 0) {
            val = 1.0f;
        } else {
            float temporal = expf(-0.1f * fabsf((float)d));
            if (spk[i] == spk[j]) {
                val = 0.8f * temporal;
            } else {
                float md = fabsf(mmask[i*3+0] - mmask[j*3+0])
                         + fabsf(mmask[i*3+1] - mmask[j*3+1])
                         + fabsf(mmask[i*3+2] - mmask[j*3+2]);
                float mod_sim = 1.0f - md * (1.0f/3.0f);
                val = 0.5f * temporal * mod_sim;
            }
        }
    }

    __shared__ float sd[BSTR];
    sd[t] = val;
    __syncthreads();
    for (int s = 256; s > 0; s >>= 1) {
        if (t < s && t + s < BSTR) sd[t] += sd[t + s];
        __syncthreads();
    }
    float inv = 1.0f / (sd[0] + 1e-8f);
    g_band[i * BSTR + t] = val * inv;
}

// ---------------------------------------------------------------------------
// Kernel 2: projection h0 = X @ Wp + bp.  f32x2, 8x2 microtile, 256 threads.
// ---------------------------------------------------------------------------
__global__ void __launch_bounds__(256) proj_kernel(
    const float* __restrict__ X, const float* __restrict__ Wp,
    const float* __restrict__ bp)
{
    __shared__ __align__(16) float As[32 * SA];
    __shared__ __align__(16) float Bs[32 * 128];
    const int m0  = blockIdx.x * RPB;
    const int tid = threadIdx.x;
    const int rg  = tid >> 6;        // 0..3 -> rows 8rg..8rg+7 (warp-uniform)
    const int cg  = tid & 63;        // 0..63 -> cols 2cg, 2cg+1

    ull acc[4][2];
#pragma unroll
    for (int a = 0; a < 4; a++) { acc[a][0] = 0ull; acc[a][1] = 0ull; }

    const int ar  = tid >> 3;        // 0..31
    const int ak4 = (tid & 7) * 4;

    for (int k0 = 0; k0 < DIN; k0 += 32) {
        // stage X^T chunk (32 rows x 32 k)
        {
            float4 v = *(const float4*)&X[(m0 + ar) * DIN + k0 + ak4];
            As[(ak4+0)*SA + ar] = v.x; As[(ak4+1)*SA + ar] = v.y;
            As[(ak4+2)*SA + ar] = v.z; As[(ak4+3)*SA + ar] = v.w;
        }
#pragma unroll
        for (int i = tid; i < 1024; i += 256) {
            int k = i >> 5, c4 = (i & 31) * 4;
            *(float4*)&Bs[k*128 + c4] = *(const float4*)&Wp[(k0 + k) * HH + c4];
        }
        __syncthreads();
#pragma unroll 8
        for (int k = 0; k < 32; k++)
            step8(acc, &As[k*SA + 8*rg], &Bs[k*128 + 2*cg]);
        __syncthreads();
    }

    float2 bb = *(const float2*)&bp[2*cg];
#pragma unroll
    for (int q = 0; q < 4; q++) {
        float2 f0 = unpk(acc[q][0]);   // col0: rows (2q, 2q+1)
        float2 f1 = unpk(acc[q][1]);   // col1
        int r_even = m0 + 8*rg + 2*q;
        float2 o0 = make_float2(f0.x + bb.x, f1.x + bb.y);
        float2 o1 = make_float2(f0.y + bb.x, f1.y + bb.y);
        *(float2*)&g_h[r_even * HH + 2*cg]           = o0;
        *(float2*)&g_ybuf[0][r_even * HH + 2*cg]     = o0;
        *(float2*)&g_h[(r_even+1) * HH + 2*cg]       = o1;
        *(float2*)&g_ybuf[0][(r_even+1) * HH + 2*cg] = o1;
    }
}

// ---------------------------------------------------------------------------
// Kernel 3: persistent ODE kernel. W1+W2 resident in smem for all 16 stages.
// Per stage: band matvec -> mlp1 (two halves) -> tanh -> mlp2 -> RK4 -> gsync.
// ---------------------------------------------------------------------------
#define SW1_FLOATS (256*128)
#define SW2_FLOATS (128*128)
#define SS_FLOATS  (CH*128 + CH*SA)          // 7872 (>= 128*SA = 4608)
#define SMEM_FLOATS (SW1_FLOATS + SW2_FLOATS + SS_FLOATS)
#define SMEM_BYTES  (SMEM_FLOATS * 4)        // 228096 B

__global__ void __launch_bounds__(256, 1) ode_kernel(
    const float* __restrict__ W1, const float* __restrict__ b1,
    const float* __restrict__ W2, const float* __restrict__ b2,
    float* __restrict__ outp)
{
    extern __shared__ __align__(16) float smem[];
    float* sW1 = smem;                     // 256x128
    float* sW2 = smem + SW1_FLOATS;        // 128x128
    float* sS  = sW2 + SW2_FLOATS;         // scratch (aliased)
    float* sY  = sS;                       // [CH][128]
    float* sB  = sS + CH*128;              // [CH][SA]
    float* sAt = sS;                       // [128][SA]  (after matvec)

    const int tid = threadIdx.x;
    const int rg  = tid >> 6;              // warp-uniform
    const int cg  = tid & 63;
    const int r0  = blockIdx.x * RPB;

    // preload weights once
#pragma unroll
    for (int i = tid; i < SW1_FLOATS/4; i += 256)
        *(float4*)&sW1[i*4] = *(const float4*)&W1[i*4];
#pragma unroll
    for (int i = tid; i < SW2_FLOATS/4; i += 256)
        *(float4*)&sW2[i*4] = *(const float4*)&W2[i*4];

    // persistent register state: rows 8rg..8rg+7, cols 2cg,2cg+1
    float hreg[8][2], rk[8][2];
#pragma unroll
    for (int i = 0; i < 8; i++) {
        float2 v = *(const float2*)&g_h[(r0 + 8*rg + i) * HH + 2*cg];
        hreg[i][0] = v.x; hreg[i][1] = v.y;
    }
    float2 b1v = *(const float2*)&b1[2*cg];
    float2 b2v = *(const float2*)&b2[2*cg];
    const float dt = 0.25f;
    __syncthreads();

#pragma unroll 1
    for (int st = 0; st < 16; st++) {
        const int s = st & 3;
        const float* __restrict__ yin  = g_ybuf[st & 1];
        float* __restrict__       yout = g_ybuf[(st + 1) & 1];

        // ---- banded matvec: macc = band @ yin (rows r0..r0+31) ----
        ull macc[4][2];
#pragma unroll
        for (int a = 0; a < 4; a++) { macc[a][0] = 0ull; macc[a][1] = 0ull; }

        for (int ch = 0; ch < NCH; ch++) {
            const int j0 = r0 - WB + ch * CH;
#pragma unroll
            for (int i = tid; i < CH * 32; i += 256) {   // y chunk: CH rows x 32 float4
                int row = i >> 5, c4 = (i & 31) * 4;
                int gj = j0 + row;
                float4 v = make_float4(0.f, 0.f, 0.f, 0.f);
                if (gj >= 0 && gj < NB)
                    v = *(const float4*)&yin[gj * HH + c4];
                *(float4*)&sY[row * 128 + c4] = v;
            }
#pragma unroll
            for (int i = tid; i < 2048; i += 256) {      // band slice [jj][r]
                int r = i >> 6, jj = i & 63;
                if (jj < CH) {
                    int gj = j0 + jj;
                    int dd = gj - (r0 + r) + WB;
                    float bv = 0.0f;
                    if ((unsigned)dd < (unsigned)BWID && (unsigned)gj < (unsigned)NB)
                        bv = g_band[(r0 + r) * BSTR + dd];
                    sB[jj * SA + r] = bv;
                }
            }
            __syncthreads();
#pragma unroll 8
            for (int j = 0; j < CH; j++)
                step8(macc, &sB[j*SA + 8*rg], &sY[j*128 + 2*cg]);
            __syncthreads();
        }

        // ---- stage hn^T (from macc registers) into sAt ----
#pragma unroll
        for (int q = 0; q < 4; q++)
#pragma unroll
            for (int c = 0; c < 2; c++) {
                float2 f = unpk(macc[q][c]);
                int col = 2*cg + c;
                sAt[col*SA + 8*rg + 2*q]     = f.x;
                sAt[col*SA + 8*rg + 2*q + 1] = f.y;
            }
        __syncthreads();

        // ---- mlp1 half A: hn part (W1 rows 128..255) ----
        ull acc1[4][2];
#pragma unroll
        for (int a = 0; a < 4; a++) { acc1[a][0] = 0ull; acc1[a][1] = 0ull; }
        {
            const float* W1b = sW1 + 128 * 128;
#pragma unroll 8
            for (int k = 0; k < 128; k++)
                step8(acc1, &sAt[k*SA + 8*rg], &W1b[k*128 + 2*cg]);
        }
        __syncthreads();

        // ---- stage y^T, mlp1 half B (W1 rows 0..127) ----
#pragma unroll
        for (int i = tid; i < 4096; i += 256) {
            int r = i >> 7, c = i & 127;
            sAt[c*SA + r] = yin[(r0 + r) * HH + c];
        }
        __syncthreads();
#pragma unroll 8
        for (int k = 0; k < 128; k++)
            step8(acc1, &sAt[k*SA + 8*rg], &sW1[k*128 + 2*cg]);
        __syncthreads();

        // ---- z = tanh(acc1 + b1), stage z^T ----
#pragma unroll
        for (int q = 0; q < 4; q++)
#pragma unroll
            for (int c = 0; c < 2; c++) {
                float2 f = unpk(acc1[q][c]);
                float bb = c ? b1v.y : b1v.x;
                int col = 2*cg + c;
                sAt[col*SA + 8*rg + 2*q]     = tanhf(f.x + bb);
                sAt[col*SA + 8*rg + 2*q + 1] = tanhf(f.y + bb);
            }
        __syncthreads();

        // ---- mlp2: k = z @ W2 + b2 ----
        ull acc2[4][2];
#pragma unroll
        for (int a = 0; a < 4; a++) { acc2[a][0] = 0ull; acc2[a][1] = 0ull; }
#pragma unroll 8
        for (int k = 0; k < 128; k++)
            step8(acc2, &sAt[k*SA + 8*rg], &sW2[k*128 + 2*cg]);

        // ---- RK4 epilogue ----
        {
            const float wq = (s == 0 || s == 3) ? dt * (1.0f/6.0f) : dt * (1.0f/3.0f);
            const float cq = (s == 2) ? dt : 0.5f * dt;
            float kvals[8][2];
#pragma unroll
            for (int q = 0; q < 4; q++)
#pragma unroll
                for (int c = 0; c < 2; c++) {
                    float2 f = unpk(acc2[q][c]);
                    float bb = c ? b2v.y : b2v.x;
                    kvals[2*q][c]   = f.x + bb;
                    kvals[2*q+1][c] = f.y + bb;
                }
            float yn[8][2];
#pragma unroll
            for (int i = 0; i < 8; i++)
#pragma unroll
                for (int c = 0; c < 2; c++) {
                    float kv = kvals[i][c];
                    if (s == 0) rk[i][c] = hreg[i][c] + wq * kv;
                    else        rk[i][c] += wq * kv;
                    if (s == 3) { hreg[i][c] = rk[i][c]; yn[i][c] = rk[i][c]; }
                    else        yn[i][c] = hreg[i][c] + cq * kv;
                }
#pragma unroll
            for (int i = 0; i < 8; i++) {
                int idx = (r0 + 8*rg + i) * HH + 2*cg;
                float2 o = make_float2(yn[i][0], yn[i][1]);
                *(float2*)&yout[idx] = o;
                if (st == 15) *(float2*)&outp[idx] = o;
            }
        }

        grid_sync_dev();
    }
}

// ---------------------------------------------------------------------------
extern "C" void kernel_launch(void* const* d_in, const int* in_sizes, int n_in,
                              void* d_out, int out_size)
{
    (void)in_sizes; (void)n_in; (void)out_size;
    const float* features = (const float*)d_in[0];
    const int*   spk      = (const int*)  d_in[1];
    const float* mmask    = (const float*)d_in[2];
    const float* Wp       = (const float*)d_in[3];
    const float* bp       = (const float*)d_in[4];
    const float* W1       = (const float*)d_in[5];
    const float* b1       = (const float*)d_in[6];
    const float* W2       = (const float*)d_in[7];
    const float* b2       = (const float*)d_in[8];
    float* out = (float*)d_out;

    static int attr_done = 0;
    if (!attr_done) {
        cudaFuncSetAttribute(ode_kernel,
                             cudaFuncAttributeMaxDynamicSharedMemorySize,
                             SMEM_BYTES);
        attr_done = 1;
    }

    build_band_kernel<<<NB, BSTR>>>(spk, mmask);
    proj_kernel<<<GRID, 256>>>(features, Wp, bp);
    ode_kernel<<<GRID, 256, SMEM_BYTES>>>(W1, b1, W2, b2, out);
}